// round 15
// baseline (speedup 1.0000x reference)
#include <cuda_runtime.h>

// L0 contraction: out[b,n] = cg_n * sum_{m in deg-block n} sphc[b,m]^2
// Row of 15 floats: [0:3) deg1, [3:8) deg2, [8:15) deg3.
// Traffic floor: 240MB read + 48MB write = 288MB (~36us @ 8TB/s spec).
// R15: tile-shrink curve still rising (15.4KB:67% -> 9.6KB:80.6% ->
//      7.7KB:82.0% DRAM). Next halving: 64-row tiles x 64 threads
//      (3.84KB smem), 32 blk/SM (HW cap) x 2 warps = 64 warps (full occ).
//      Compute = exactly 1 row/thread; block-staged float4 __ldcs loads,
//      one barrier, direct per-row __stcs stores (384B contig per warp).

constexpr int THREADS = 64;
constexpr int ROWS_PER_BLOCK = 64;
constexpr int M = 15;
constexpr int NV = ROWS_PER_BLOCK * M / 4;   // 240 float4 in

__global__ __launch_bounds__(THREADS, 32) void l0_contraction_kernel(
    const float* __restrict__ sphc,
    const float* __restrict__ cg,
    float* __restrict__ out,
    int B)
{
    __shared__ float s_in[ROWS_PER_BLOCK * M];   // 3840 B

    const float c0 = __ldg(cg + 0);  // 1/sqrt(3)
    const float c1 = __ldg(cg + 3);  // 1/sqrt(5)
    const float c2 = __ldg(cg + 8);  // 1/sqrt(7)

    const long long row0 = (long long)blockIdx.x * ROWS_PER_BLOCK;
    const int tid = threadIdx.x;
    const int nrows = (int)min((long long)ROWS_PER_BLOCK, (long long)B - row0);

    if (nrows == ROWS_PER_BLOCK) {
        // ---- full tile ----
        // 64 rows * 60B = 3840B; tile base 16B-aligned (3840%16==0).
        const float4* gin = reinterpret_cast<const float4*>(sphc + row0 * M);
        float4* s4 = reinterpret_cast<float4*>(s_in);
        #pragma unroll
        for (int i = 0; i < (NV + THREADS - 1) / THREADS; i++) {  // 4 iters (last 48 thr)
            const int idx = tid + i * THREADS;
            if (idx < NV) s4[idx] = __ldcs(gin + idx);  // evict-first stream
        }
        __syncthreads();

        // Exactly one row per thread.
        const float* x = s_in + tid * M;         // stride 15: conflict-free
        float a = x[0]*x[0] + x[1]*x[1] + x[2]*x[2];
        float b = x[3]*x[3] + x[4]*x[4] + x[5]*x[5] + x[6]*x[6] + x[7]*x[7];
        float c = x[8]*x[8] + x[9]*x[9] + x[10]*x[10] + x[11]*x[11]
                + x[12]*x[12] + x[13]*x[13] + x[14]*x[14];
        float* o = out + (row0 + tid) * 3;       // warp: 384B contiguous
        __stcs(o + 0, a * c0);
        __stcs(o + 1, b * c1);
        __stcs(o + 2, c * c2);
    } else {
        // ---- tail tile: scalar, guarded ----
        const float* gin = sphc + row0 * M;
        const int nf = nrows * M;
        for (int i = tid; i < nf; i += THREADS) s_in[i] = gin[i];
        __syncthreads();

        for (int r = tid; r < nrows; r += THREADS) {
            const float* x = s_in + r * M;
            float a = x[0]*x[0] + x[1]*x[1] + x[2]*x[2];
            float b = x[3]*x[3] + x[4]*x[4] + x[5]*x[5] + x[6]*x[6] + x[7]*x[7];
            float c = x[8]*x[8] + x[9]*x[9] + x[10]*x[10] + x[11]*x[11]
                    + x[12]*x[12] + x[13]*x[13] + x[14]*x[14];
            float* o = out + (row0 + r) * 3;
            o[0] = a * c0;
            o[1] = b * c1;
            o[2] = c * c2;
        }
    }
}

extern "C" void kernel_launch(void* const* d_in, const int* in_sizes, int n_in,
                              void* d_out, int out_size) {
    const float* sphc = (const float*)d_in[0];
    const float* cg   = (const float*)d_in[1];
    // d_in[2] = segment_ids (structure is compile-time: 3/5/7 blocks)
    float* out = (float*)d_out;

    const int B = in_sizes[0] / M;  // 4,000,000
    const int grid = (B + ROWS_PER_BLOCK - 1) / ROWS_PER_BLOCK;  // 62500
    l0_contraction_kernel<<<grid, THREADS>>>(sphc, cg, out, B);
}